// round 15
// baseline (speedup 1.0000x reference)
#include <cuda_runtime.h>
#include <cuda_fp16.h>
#include <math.h>
#include <stdint.h>

#define NB    512
#define NT    98
#define DIMC  512
#define NH    16
#define HD    32
#define NWIN  64
#define MROWS (NB*NT)                 // 50176
#define QK_SCALE 0.17677669529663687f

// ---------------- scratch (device globals; no runtime alloc) ---------------
__device__ __align__(16) __half g_x [(size_t)MROWS*DIMC];    // x fp16
__device__ __align__(16) __half g_w [(size_t)3*DIMC*DIMC];   // qkv_w fp16
__device__ __align__(16) __half g_p [(size_t)DIMC*DIMC];     // proj_w fp16
__device__ __align__(16) __half g_o [(size_t)MROWS*DIMC];    // attn out fp16

// q single, k hi/lo, v single fp16; layout [(b*NH+h)*NT + n][HD]
__device__ __align__(16) __half g_q [(size_t)NB*NH*NT*HD];
__device__ __align__(16) __half g_kh[(size_t)NB*NH*NT*HD];
__device__ __align__(16) __half g_kl[(size_t)NB*NH*NT*HD];
__device__ __align__(16) __half g_v [(size_t)NB*NH*NT*HD];

__device__ float g_bias[NH*NT*NT];

// ---------------- helpers ----------------------------------------------------
__device__ __forceinline__ uint32_t smem_u32(const void* p) {
    uint32_t a;
    asm("{ .reg .u64 t; cvta.to.shared.u64 t, %1; cvt.u32.u64 %0, t; }"
        : "=r"(a) : "l"(p));
    return a;
}
__device__ __forceinline__ void ldsm_x4(uint32_t& r0, uint32_t& r1,
                                        uint32_t& r2, uint32_t& r3, uint32_t addr) {
    asm volatile("ldmatrix.sync.aligned.m8n8.x4.shared.b16 {%0,%1,%2,%3}, [%4];"
                 : "=r"(r0), "=r"(r1), "=r"(r2), "=r"(r3) : "r"(addr));
}
__device__ __forceinline__ void ldsm_x4_t(uint32_t& r0, uint32_t& r1,
                                          uint32_t& r2, uint32_t& r3, uint32_t addr) {
    asm volatile("ldmatrix.sync.aligned.m8n8.x4.trans.shared.b16 {%0,%1,%2,%3}, [%4];"
                 : "=r"(r0), "=r"(r1), "=r"(r2), "=r"(r3) : "r"(addr));
}
__device__ __forceinline__ void mma_f16(float* c, const uint32_t* a, const uint32_t* b) {
    asm volatile(
        "mma.sync.aligned.m16n8k16.row.col.f32.f16.f16.f32 "
        "{%0,%1,%2,%3}, {%4,%5,%6,%7}, {%8,%9}, {%0,%1,%2,%3};"
        : "+f"(c[0]), "+f"(c[1]), "+f"(c[2]), "+f"(c[3])
        : "r"(a[0]), "r"(a[1]), "r"(a[2]), "r"(a[3]), "r"(b[0]), "r"(b[1]));
}
__device__ __forceinline__ void cpa16(uint32_t saddr, const void* g) {
    asm volatile("cp.async.cg.shared.global [%0], [%1], 16;"
                 :: "r"(saddr), "l"(g) : "memory");
}
__device__ __forceinline__ uint32_t packh2(float a, float b) {
    __half2 h = __halves2half2(__float2half_rn(a), __float2half_rn(b));
    return *(uint32_t*)&h;
}
// 64B-row tile swizzle (attention tiles)
__device__ __forceinline__ uint32_t sw_off(int row, int q) {
    return (uint32_t)(row * 64 + ((q ^ ((row >> 1) & 3)) << 4));
}
// 128B-row tile swizzle (GEMM tiles)
__device__ __forceinline__ uint32_t sw128o(int row, int q) {
    return (uint32_t)(row * 128 + ((q ^ (row & 7)) << 4));
}

// ---------------- fused preprocessing: converts + bias gather -----------------
#define N8X  (MROWS*DIMC/8)
#define N8W  (3*DIMC*DIMC/8)
#define N8P  (DIMC*DIMC/8)
#define BX   (N8X/256)
#define BW   (N8W/256)
#define BP   (N8P/256)
#define BBIAS ((NH*NT*NT + 255)/256)
#define PRE_BLOCKS (BX + BW + BP + BBIAS)

__global__ void pre_kernel(const float* __restrict__ x,
                           const float* __restrict__ qkv_w,
                           const float* __restrict__ proj_w,
                           const float* __restrict__ bt,
                           const int*   __restrict__ ri) {
    int blk = blockIdx.x;
    if (blk < BX + BW + BP) {
        const float* src;
        __half2* dst;
        int i;
        if (blk < BX)            { src = x;      dst = (__half2*)g_x; i = blk*256 + threadIdx.x; }
        else if (blk < BX + BW)  { src = qkv_w;  dst = (__half2*)g_w; i = (blk-BX)*256 + threadIdx.x; }
        else                     { src = proj_w; dst = (__half2*)g_p; i = (blk-BX-BW)*256 + threadIdx.x; }
        float4 a = ((const float4*)src)[2*i];
        float4 b = ((const float4*)src)[2*i + 1];
        dst[4*i + 0] = __halves2half2(__float2half_rn(a.x), __float2half_rn(a.y));
        dst[4*i + 1] = __halves2half2(__float2half_rn(a.z), __float2half_rn(a.w));
        dst[4*i + 2] = __halves2half2(__float2half_rn(b.x), __float2half_rn(b.y));
        dst[4*i + 3] = __halves2half2(__float2half_rn(b.z), __float2half_rn(b.w));
    } else {
        int idx = (blk - BX - BW - BP)*256 + threadIdx.x;
        if (idx < NH*NT*NT) {
            int h  = idx / (NT*NT);
            int ij = idx - h*(NT*NT);
            g_bias[idx] = bt[ri[ij]*NH + h];
        }
    }
}

// ---------------- HMMA fp16 GEMM: 128x256 tile, 512 thr, 3-stage cp.async ------
// C[M,N] = A[M,512] @ B[N,512]^T + bias[N]
// MODE 1: A=g_x, B=g_w (N=1536), scatter q/k/v
// MODE 0: A=g_o, B=g_p (N=512), fp32 write to d_out
#define KCH      64
#define NCHUNK   (DIMC / KCH)          // 8
#define A_TILE_B 16384                 // 128 rows x 128B
#define B_TILE_B 32768                 // 256 rows x 128B
#define STAGE_B  (A_TILE_B + B_TILE_B) // 48 KB
#define NSTAGE   3
#define SMEM_GEMM (NSTAGE * STAGE_B)   // 144 KB

template<int MODE>
__global__ __launch_bounds__(512, 1)
void gemm_mma(const float* __restrict__ bias, float* __restrict__ C) {
    extern __shared__ char smem[];
    const int tid  = threadIdx.x;
    const int lane = tid & 31;
    const int wid  = tid >> 5;            // 0..15
    const int wm   = wid >> 3;            // 0..1  -> m offset 64*wm
    const int wn   = wid & 7;             // 0..7  -> n offset 32*wn
    const int m0 = blockIdx.y * 128;
    const int n0 = blockIdx.x * 256;

    const __half* A = (MODE == 1) ? g_x : g_o;
    const __half* B = (MODE == 1) ? g_w : g_p;

    const uint32_t sb = smem_u32(smem);

    float acc[4][4][4];
    #pragma unroll
    for (int i = 0; i < 4; i++)
        #pragma unroll
        for (int j = 0; j < 4; j++)
            #pragma unroll
            for (int k = 0; k < 4; k++) acc[i][j][k] = 0.f;

    // A: 1024 16B units (2/thread); B: 2048 units (4/thread)
    #define FILL_STAGE(SBASE, K0)                                               \
        {                                                                       \
            _Pragma("unroll")                                                   \
            for (int t = 0; t < 2; t++) {                                       \
                int u = tid + 512*t;                                            \
                int row = u >> 3, q = u & 7;                                    \
                cpa16((SBASE) + sw128o(row, q),                                 \
                      A + (size_t)(m0 + row)*DIMC + (K0) + q*8);                \
            }                                                                   \
            _Pragma("unroll")                                                   \
            for (int t = 0; t < 4; t++) {                                       \
                int u = tid + 512*t;                                            \
                int row = u >> 3, q = u & 7;                                    \
                cpa16((SBASE) + A_TILE_B + sw128o(row, q),                      \
                      B + (size_t)(n0 + row)*DIMC + (K0) + q*8);                \
            }                                                                   \
        }

    FILL_STAGE(sb + 0*STAGE_B, 0);
    asm volatile("cp.async.commit_group;" ::: "memory");
    FILL_STAGE(sb + 1*STAGE_B, KCH);
    asm volatile("cp.async.commit_group;" ::: "memory");

    const int lr  = lane & 15;
    const int lq2 = lane >> 4;
    int stage = 0;

    for (int c = 0; c < NCHUNK; c++) {
        asm volatile("cp.async.wait_group 1;" ::: "memory");
        __syncthreads();

        if (c + 2 < NCHUNK) {
            int ps = stage + 2; if (ps >= NSTAGE) ps -= NSTAGE;
            FILL_STAGE(sb + ps*STAGE_B, (c + 2)*KCH);
        }
        asm volatile("cp.async.commit_group;" ::: "memory");

        const uint32_t tba = sb + (uint32_t)stage * STAGE_B;
        #pragma unroll
        for (int ks = 0; ks < 4; ks++) {
            const int qq = ks*2 + lq2;
            uint32_t af[4][4], bf[4][2];
            #pragma unroll
            for (int mt = 0; mt < 4; mt++) {
                uint32_t off = sw128o(wm*64 + mt*16 + lr, qq);
                ldsm_x4(af[mt][0], af[mt][1], af[mt][2], af[mt][3], tba + off);
            }
            #pragma unroll
            for (int g2 = 0; g2 < 2; g2++) {
                uint32_t off = sw128o(wn*32 + g2*16 + lr, qq);
                uint32_t t0, t1, t2, t3;
                ldsm_x4(t0, t1, t2, t3, tba + A_TILE_B + off);
                bf[2*g2][0] = t0; bf[2*g2][1] = t2;
                bf[2*g2+1][0] = t1; bf[2*g2+1][1] = t3;
            }
            #pragma unroll
            for (int mt = 0; mt < 4; mt++)
                #pragma unroll
                for (int nt = 0; nt < 4; nt++)
                    mma_f16(acc[mt][nt], af[mt], bf[nt]);
        }
        __syncthreads();
        stage++; if (stage >= NSTAGE) stage -= NSTAGE;
    }
    #undef FILL_STAGE

    // ---- epilogue
    if (MODE == 0) {
        #pragma unroll
        for (int mt = 0; mt < 4; mt++)
            #pragma unroll
            for (int nt = 0; nt < 4; nt++) {
                const int col = n0 + wn*32 + nt*8 + (lane & 3)*2;
                const float b0 = bias[col], b1 = bias[col + 1];
                #pragma unroll
                for (int half = 0; half < 2; half++) {
                    const int row = m0 + wm*64 + mt*16 + (lane >> 2) + half*8;
                    *(float2*)(C + (size_t)row*DIMC + col) =
                        make_float2(acc[mt][nt][2*half] + b0,
                                    acc[mt][nt][2*half + 1] + b1);
                }
            }
    } else {
        #pragma unroll
        for (int mt = 0; mt < 4; mt++)
            #pragma unroll
            for (int half = 0; half < 2; half++) {
                const int row = m0 + wm*64 + mt*16 + (lane >> 2) + half*8;
                const int b = row / NT;
                const int n = row - b*NT;
                const size_t base = ((size_t)b*NH*NT + n)*HD;
                #pragma unroll
                for (int nt = 0; nt < 4; nt++) {
                    const int col = n0 + wn*32 + nt*8 + (lane & 3)*2;
                    float vx = acc[mt][nt][2*half + 0] + bias[col];
                    float vy = acc[mt][nt][2*half + 1] + bias[col + 1];
                    const int which = col >> 9;          // 0=q 1=k 2=v
                    const int head  = (col & 511) >> 5;
                    const int d     = col & 31;
                    const size_t o  = base + (size_t)head*(NT*HD) + d;
                    if (which == 0) {
                        *(__half2*)(g_q + o) =
                            __halves2half2(__float2half_rn(vx * QK_SCALE),
                                           __float2half_rn(vy * QK_SCALE));
                    } else if (which == 2) {
                        *(__half2*)(g_v + o) =
                            __halves2half2(__float2half_rn(vx), __float2half_rn(vy));
                    } else {
                        __half h0 = __float2half_rn(vx);
                        __half h1 = __float2half_rn(vy);
                        __half l0 = __float2half_rn(vx - __half2float(h0));
                        __half l1 = __float2half_rn(vy - __half2float(h1));
                        *(__half2*)(g_kh + o) = __halves2half2(h0, h1);
                        *(__half2*)(g_kl + o) = __halves2half2(l0, l1);
                    }
                }
            }
    }
}

// ---------------- HMMA attention (R13 version): register-resident P ------------
// 224 threads = 7 warps; warp wid owns output rows wid*16..wid*16+15.
#define AP      112
#define AT_Q  0
#define AT_KH (AP*64)
#define AT_KL (2*AP*64)
#define AT_V  (3*AP*64)
#define AT_BYTES (4*AP*64)      // 28672

__global__ __launch_bounds__(224)
void attn_mma_kernel(const float* __restrict__ mask) {
    extern __shared__ char sm[];
    const int tid  = threadIdx.x;
    const int lane = tid & 31;
    const int wid  = tid >> 5;
    const int bh = blockIdx.x;
    const int b  = bh >> 4;
    const int h  = bh & 15;
    const int w  = b & (NWIN - 1);
    const uint32_t sb = smem_u32(sm);

    // ---- fill q, k(hi/lo), v tiles; zero pad rows 98..111
    {
        const __half* gsrc[4] = { g_q, g_kh, g_kl, g_v };
        const size_t gbase = (size_t)bh * (NT*HD);
        for (int c = tid; c < 4*AP*4; c += 224) {
            int mat = c / (AP*4);
            int rem = c % (AP*4);
            int row = rem >> 2, q = rem & 3;
            uint4 val = make_uint4(0, 0, 0, 0);
            if (row < NT)
                val = *(const uint4*)(gsrc[mat] + gbase + (size_t)row*HD + q*8);
            *(uint4*)(sm + mat*AP*64 + sw_off(row, q)) = val;
        }
    }
    __syncthreads();

    const int lr  = lane & 15;
    const int lq2 = lane >> 4;

    // ---- S = Q K^T (q single, k hi/lo)
    uint32_t qf[2][4];
    #pragma unroll
    for (int ks = 0; ks < 2; ks++) {
        uint32_t off = sw_off(wid*16 + lr, 2*ks + lq2);
        ldsm_x4(qf[ks][0], qf[ks][1], qf[ks][2], qf[ks][3], sb + AT_Q + off);
    }
    float c[7][2][4];
    #pragma unroll
    for (int nt = 0; nt < 7; nt++)
        #pragma unroll
        for (int n8 = 0; n8 < 2; n8++)
            #pragma unroll
            for (int e = 0; e < 4; e++) c[nt][n8][e] = 0.f;

    #pragma unroll
    for (int nt = 0; nt < 7; nt++) {
        #pragma unroll
        for (int ks = 0; ks < 2; ks++) {
            uint32_t t0, t1, t2, t3, u0, u1, u2, u3;
            uint32_t off = sw_off(nt*16 + lr, 2*ks + lq2);
            ldsm_x4(t0, t1, t2, t3, sb + AT_KH + off);
            ldsm_x4(u0, u1, u2, u3, sb + AT_KL + off);
            uint32_t kh0[2] = {t0, t2}, kh1[2] = {t1, t3};
            uint32_t kl0[2] = {u0, u2}, kl1[2] = {u1, u3};
            mma_f16(c[nt][0], qf[ks], kh0);
            mma_f16(c[nt][0], qf[ks], kl0);
            mma_f16(c[nt][1], qf[ks], kh1);
            mma_f16(c[nt][1], qf[ks], kl1);
        }
    }

    // ---- fused bias+mask, register softmax
    const int i0 = wid*16 + (lane >> 2);
    const int i1 = i0 + 8;
    const float* bi = g_bias + (size_t)h * (NT*NT);
    const float* mk = mask   + (size_t)w * (NT*NT);
    #pragma unroll
    for (int nt = 0; nt < 7; nt++)
        #pragma unroll
        for (int n8 = 0; n8 < 2; n8++) {
            int col = nt*16 + n8*8 + (lane & 3)*2;
            if (col < NT && i0 < NT) {
                float2 bv = *(const float2*)(bi + (size_t)i0*NT + col);
                float2 mv = *(const float2*)(mk + (size_t)i0*NT + col);
                c[nt][n8][0] += bv.x + mv.x;
                c[nt][n8][1] += bv.y + mv.y;
            } else { c[nt][n8][0] = -1e30f; c[nt][n8][1] = -1e30f; }
            if (col < NT && i1 < NT) {
                float2 bv = *(const float2*)(bi + (size_t)i1*NT + col);
                float2 mv = *(const float2*)(mk + (size_t)i1*NT + col);
                c[nt][n8][2] += bv.x + mv.x;
                c[nt][n8][3] += bv.y + mv.y;
            } else { c[nt][n8][2] = -1e30f; c[nt][n8][3] = -1e30f; }
        }

    float mx0 = -1e30f, mx1 = -1e30f;
    #pragma unroll
    for (int nt = 0; nt < 7; nt++)
        #pragma unroll
        for (int n8 = 0; n8 < 2; n8++) {
            mx0 = fmaxf(mx0, fmaxf(c[nt][n8][0], c[nt][n8][1]));
            mx1 = fmaxf(mx1, fmaxf(c[nt][n8][2], c[nt][n8][3]));
        }
    #pragma unroll
    for (int off = 1; off <= 2; off <<= 1) {
        mx0 = fmaxf(mx0, __shfl_xor_sync(0xffffffffu, mx0, off));
        mx1 = fmaxf(mx1, __shfl_xor_sync(0xffffffffu, mx1, off));
    }
    float s0 = 0.f, s1 = 0.f;
    #pragma unroll
    for (int nt = 0; nt < 7; nt++)
        #pragma unroll
        for (int n8 = 0; n8 < 2; n8++) {
            float e0 = __expf(c[nt][n8][0] - mx0);
            float e1 = __expf(c[nt][n8][1] - mx0);
            float e2 = __expf(c[nt][n8][2] - mx1);
            float e3 = __expf(c[nt][n8][3] - mx1);
            c[nt][n8][0] = e0; c[nt][n8][1] = e1;
            c[nt][n8][2] = e2; c[nt][n8][3] = e3;
            s0 += e0 + e1; s1 += e2 + e3;
        }
    #pragma unroll
    for (int off = 1; off <= 2; off <<= 1) {
        s0 += __shfl_xor_sync(0xffffffffu, s0, off);
        s1 += __shfl_xor_sync(0xffffffffu, s1, off);
    }
    const float r0 = 1.f / s0, r1 = 1.f / s1;

    // ---- convert P c-frags -> PV a-frags in registers
    uint32_t pa[7][4];
    #pragma unroll
    for (int nt = 0; nt < 7; nt++) {
        pa[nt][0] = packh2(c[nt][0][0] * r0, c[nt][0][1] * r0);
        pa[nt][1] = packh2(c[nt][0][2] * r1, c[nt][0][3] * r1);
        pa[nt][2] = packh2(c[nt][1][0] * r0, c[nt][1][1] * r0);
        pa[nt][3] = packh2(c[nt][1][2] * r1, c[nt][1][3] * r1);
    }

    // ---- out = P V
    float oc[4][4];
    #pragma unroll
    for (int j = 0; j < 4; j++)
        #pragma unroll
        for (int e = 0; e < 4; e++) oc[j][e] = 0.f;

    #pragma unroll
    for (int kt = 0; kt < 7; kt++) {
        #pragma unroll
        for (int vt = 0; vt < 2; vt++) {
            uint32_t t0, t1, t2, t3;
            ldsm_x4_t(t0, t1, t2, t3, sb + AT_V + sw_off(kt*16 + lr, vt*2 + lq2));
            uint32_t b0[2] = {t0, t1}, b1[2] = {t2, t3};
            mma_f16(oc[vt*2 + 0], pa[kt], b0);
            mma_f16(oc[vt*2 + 1], pa[kt], b1);
        }
    }

    // ---- store (fp16, proj-input layout)
    #pragma unroll
    for (int j = 0; j < 4; j++) {
        const int d = j*8 + (lane & 3)*2;
        if (i0 < NT)
            *(__half2*)(g_o + (size_t)(b*NT + i0)*DIMC + h*HD + d) =
                __halves2half2(__float2half_rn(oc[j][0]), __float2half_rn(oc[j][1]));
        if (i1 < NT)
            *(__half2*)(g_o + (size_t)(b*NT + i1)*DIMC + h*HD + d) =
                __halves2half2(__float2half_rn(oc[j][2]), __float2half_rn(oc[j][3]));
    }
}

// ---------------- launch --------------------------------------------------------
extern "C" void kernel_launch(void* const* d_in, const int* in_sizes, int n_in,
                              void* d_out, int out_size) {
    const float* x          = (const float*)d_in[0];
    const float* mask       = (const float*)d_in[1];
    const float* qkv_w      = (const float*)d_in[2];
    const float* qkv_b      = (const float*)d_in[3];
    const float* proj_w     = (const float*)d_in[4];
    const float* proj_b     = (const float*)d_in[5];
    const float* bias_table = (const float*)d_in[6];
    const int*   rel_index  = (const int*)  d_in[7];
    float* out = (float*)d_out;

    cudaFuncSetAttribute(attn_mma_kernel,
                         cudaFuncAttributeMaxDynamicSharedMemorySize, AT_BYTES);
    cudaFuncSetAttribute(gemm_mma<0>,
                         cudaFuncAttributeMaxDynamicSharedMemorySize, SMEM_GEMM);
    cudaFuncSetAttribute(gemm_mma<1>,
                         cudaFuncAttributeMaxDynamicSharedMemorySize, SMEM_GEMM);

    pre_kernel<<<PRE_BLOCKS, 256>>>(x, qkv_w, proj_w, bias_table, rel_index);
    gemm_mma<1><<<dim3(3*DIMC/256, MROWS/128), 512, SMEM_GEMM>>>(qkv_b, nullptr);
    attn_mma_kernel<<<NB*NH, 224, AT_BYTES>>>(mask);
    gemm_mma<0><<<dim3(DIMC/256, MROWS/128), 512, SMEM_GEMM>>>(proj_b, out);
}

// round 16
// speedup vs baseline: 1.2061x; 1.2061x over previous
#include <cuda_runtime.h>
#include <cuda_fp16.h>
#include <math.h>
#include <stdint.h>

#define NB    512
#define NT    98
#define DIMC  512
#define NH    16
#define HD    32
#define NWIN  64
#define MROWS (NB*NT)                 // 50176
#define QK_SCALE 0.17677669529663687f

// ---------------- scratch (device globals; no runtime alloc) ---------------
__device__ __align__(16) __half g_x [(size_t)MROWS*DIMC];    // x fp16
__device__ __align__(16) __half g_w [(size_t)3*DIMC*DIMC];   // qkv_w fp16
__device__ __align__(16) __half g_p [(size_t)DIMC*DIMC];     // proj_w fp16
__device__ __align__(16) __half g_o [(size_t)MROWS*DIMC];    // attn out fp16

// q single, k hi/lo, v single fp16; layout [(b*NH+h)*NT + n][HD]
__device__ __align__(16) __half g_q [(size_t)NB*NH*NT*HD];
__device__ __align__(16) __half g_kh[(size_t)NB*NH*NT*HD];
__device__ __align__(16) __half g_kl[(size_t)NB*NH*NT*HD];
__device__ __align__(16) __half g_v [(size_t)NB*NH*NT*HD];

// combined bias+mask, fp16: [w][h][i][j]
__device__ __align__(16) __half g_bm[(size_t)NWIN*NH*NT*NT];

// ---------------- helpers ----------------------------------------------------
__device__ __forceinline__ uint32_t smem_u32(const void* p) {
    uint32_t a;
    asm("{ .reg .u64 t; cvta.to.shared.u64 t, %1; cvt.u32.u64 %0, t; }"
        : "=r"(a) : "l"(p));
    return a;
}
__device__ __forceinline__ void ldsm_x4(uint32_t& r0, uint32_t& r1,
                                        uint32_t& r2, uint32_t& r3, uint32_t addr) {
    asm volatile("ldmatrix.sync.aligned.m8n8.x4.shared.b16 {%0,%1,%2,%3}, [%4];"
                 : "=r"(r0), "=r"(r1), "=r"(r2), "=r"(r3) : "r"(addr));
}
__device__ __forceinline__ void ldsm_x4_t(uint32_t& r0, uint32_t& r1,
                                          uint32_t& r2, uint32_t& r3, uint32_t addr) {
    asm volatile("ldmatrix.sync.aligned.m8n8.x4.trans.shared.b16 {%0,%1,%2,%3}, [%4];"
                 : "=r"(r0), "=r"(r1), "=r"(r2), "=r"(r3) : "r"(addr));
}
__device__ __forceinline__ void mma_f16(float* c, const uint32_t* a, const uint32_t* b) {
    asm volatile(
        "mma.sync.aligned.m16n8k16.row.col.f32.f16.f16.f32 "
        "{%0,%1,%2,%3}, {%4,%5,%6,%7}, {%8,%9}, {%0,%1,%2,%3};"
        : "+f"(c[0]), "+f"(c[1]), "+f"(c[2]), "+f"(c[3])
        : "r"(a[0]), "r"(a[1]), "r"(a[2]), "r"(a[3]), "r"(b[0]), "r"(b[1]));
}
__device__ __forceinline__ void cpa16(uint32_t saddr, const void* g) {
    asm volatile("cp.async.cg.shared.global [%0], [%1], 16;"
                 :: "r"(saddr), "l"(g) : "memory");
}
__device__ __forceinline__ uint32_t packh2(float a, float b) {
    __half2 h = __halves2half2(__float2half_rn(a), __float2half_rn(b));
    return *(uint32_t*)&h;
}
// 64B-row tile swizzle (attention tiles)
__device__ __forceinline__ uint32_t sw_off(int row, int q) {
    return (uint32_t)(row * 64 + ((q ^ ((row >> 1) & 3)) << 4));
}
// 128B-row tile swizzle (GEMM tiles)
__device__ __forceinline__ uint32_t sw128o(int row, int q) {
    return (uint32_t)(row * 128 + ((q ^ (row & 7)) << 4));
}

// ---------------- fused preprocessing: converts + combined bias/mask ----------
#define N8X  (MROWS*DIMC/8)
#define N8W  (3*DIMC*DIMC/8)
#define N8P  (DIMC*DIMC/8)
#define BX   (N8X/256)
#define BW   (N8W/256)
#define BP   (N8P/256)
#define BBM  (NWIN*NH)               // 1024 blocks, one per (w,h)
#define PRE_BLOCKS (BX + BW + BP + BBM)

__global__ void pre_kernel(const float* __restrict__ x,
                           const float* __restrict__ qkv_w,
                           const float* __restrict__ proj_w,
                           const float* __restrict__ mask,
                           const float* __restrict__ bt,
                           const int*   __restrict__ ri) {
    int blk = blockIdx.x;
    if (blk < BX + BW + BP) {
        const float* src;
        __half2* dst;
        int i;
        if (blk < BX)            { src = x;      dst = (__half2*)g_x; i = blk*256 + threadIdx.x; }
        else if (blk < BX + BW)  { src = qkv_w;  dst = (__half2*)g_w; i = (blk-BX)*256 + threadIdx.x; }
        else                     { src = proj_w; dst = (__half2*)g_p; i = (blk-BX-BW)*256 + threadIdx.x; }
        float4 a = ((const float4*)src)[2*i];
        float4 b = ((const float4*)src)[2*i + 1];
        dst[4*i + 0] = __halves2half2(__float2half_rn(a.x), __float2half_rn(a.y));
        dst[4*i + 1] = __halves2half2(__float2half_rn(a.z), __float2half_rn(a.w));
        dst[4*i + 2] = __halves2half2(__float2half_rn(b.x), __float2half_rn(b.y));
        dst[4*i + 3] = __halves2half2(__float2half_rn(b.z), __float2half_rn(b.w));
    } else {
        // combined bias+mask plane for one (w,h)
        const int blk2 = blk - (BX + BW + BP);
        const int w = blk2 >> 4;
        const int h = blk2 & 15;
        const float* mk = mask + (size_t)w * (NT*NT);
        __half* dst = g_bm + (size_t)blk2 * (NT*NT);
        for (int ij = threadIdx.x; ij < NT*NT; ij += 256)
            dst[ij] = __float2half_rn(bt[ri[ij]*NH + h] + mk[ij]);
    }
}

// ---------------- HMMA fp16 GEMM (R13 shape; redundant barrier removed) --------
#define KCH      64
#define NCHUNK   (DIMC / KCH)        // 8
#define TILE_B2  16384               // 128 rows x 128B
#define STAGE_B  (2 * TILE_B2)       // A + B = 32 KB
#define NSTAGE   3
#define SMEM_GEMM (NSTAGE * STAGE_B) // 96 KB

template<int MODE>
__global__ __launch_bounds__(256, 2)
void gemm_mma(const float* __restrict__ bias, float* __restrict__ C) {
    extern __shared__ char smem[];
    const int tid  = threadIdx.x;
    const int lane = tid & 31;
    const int wid  = tid >> 5;
    const int wm   = wid >> 2;
    const int wn   = wid & 3;
    const int m0 = blockIdx.y * 128;
    const int n0 = blockIdx.x * 128;

    const __half* A = (MODE == 1) ? g_x : g_o;
    const __half* B = (MODE == 1) ? g_w : g_p;

    const uint32_t sb = smem_u32(smem);

    float acc[4][4][4];
    #pragma unroll
    for (int i = 0; i < 4; i++)
        #pragma unroll
        for (int j = 0; j < 4; j++)
            #pragma unroll
            for (int k = 0; k < 4; k++) acc[i][j][k] = 0.f;

    #define FILL_STAGE(SBASE, K0)                                               \
        {                                                                       \
            _Pragma("unroll")                                                   \
            for (int t = 0; t < 4; t++) {                                       \
                int u = tid + 256*t;                                            \
                int row = u >> 3, q = u & 7;                                    \
                cpa16((SBASE) + sw128o(row, q),                                 \
                      A + (size_t)(m0 + row)*DIMC + (K0) + q*8);                \
                cpa16((SBASE) + TILE_B2 + sw128o(row, q),                       \
                      B + (size_t)(n0 + row)*DIMC + (K0) + q*8);                \
            }                                                                   \
        }

    FILL_STAGE(sb + 0*STAGE_B, 0);
    asm volatile("cp.async.commit_group;" ::: "memory");
    FILL_STAGE(sb + 1*STAGE_B, KCH);
    asm volatile("cp.async.commit_group;" ::: "memory");

    const int lr  = lane & 15;
    const int lq2 = lane >> 4;
    int stage = 0;

    for (int c = 0; c < NCHUNK; c++) {
        asm volatile("cp.async.wait_group 1;" ::: "memory");
        __syncthreads();   // orders: prior compute reads done + current data landed

        if (c + 2 < NCHUNK) {
            int ps = stage + 2; if (ps >= NSTAGE) ps -= NSTAGE;
            FILL_STAGE(sb + ps*STAGE_B, (c + 2)*KCH);
        }
        asm volatile("cp.async.commit_group;" ::: "memory");

        const uint32_t tba = sb + (uint32_t)stage * STAGE_B;
        #pragma unroll
        for (int ks = 0; ks < 4; ks++) {
            const int qq = ks*2 + lq2;
            uint32_t af[4][4], bf[4][2];
            #pragma unroll
            for (int mt = 0; mt < 4; mt++) {
                uint32_t off = sw128o(wm*64 + mt*16 + lr, qq);
                ldsm_x4(af[mt][0], af[mt][1], af[mt][2], af[mt][3], tba + off);
            }
            #pragma unroll
            for (int g2 = 0; g2 < 2; g2++) {
                uint32_t off = sw128o(wn*32 + g2*16 + lr, qq);
                uint32_t t0, t1, t2, t3;
                ldsm_x4(t0, t1, t2, t3, tba + TILE_B2 + off);
                bf[2*g2][0] = t0; bf[2*g2][1] = t2;
                bf[2*g2+1][0] = t1; bf[2*g2+1][1] = t3;
            }
            #pragma unroll
            for (int mt = 0; mt < 4; mt++)
                #pragma unroll
                for (int nt = 0; nt < 4; nt++)
                    mma_f16(acc[mt][nt], af[mt], bf[nt]);
        }
        stage++; if (stage >= NSTAGE) stage -= NSTAGE;
    }
    #undef FILL_STAGE

    // ---- epilogue
    if (MODE == 0) {
        #pragma unroll
        for (int mt = 0; mt < 4; mt++)
            #pragma unroll
            for (int nt = 0; nt < 4; nt++) {
                const int col = n0 + wn*32 + nt*8 + (lane & 3)*2;
                const float b0 = bias[col], b1 = bias[col + 1];
                #pragma unroll
                for (int half = 0; half < 2; half++) {
                    const int row = m0 + wm*64 + mt*16 + (lane >> 2) + half*8;
                    *(float2*)(C + (size_t)row*DIMC + col) =
                        make_float2(acc[mt][nt][2*half] + b0,
                                    acc[mt][nt][2*half + 1] + b1);
                }
            }
    } else {
        #pragma unroll
        for (int mt = 0; mt < 4; mt++)
            #pragma unroll
            for (int half = 0; half < 2; half++) {
                const int row = m0 + wm*64 + mt*16 + (lane >> 2) + half*8;
                const int b = row / NT;
                const int n = row - b*NT;
                const size_t base = ((size_t)b*NH*NT + n)*HD;
                #pragma unroll
                for (int nt = 0; nt < 4; nt++) {
                    const int col = n0 + wn*32 + nt*8 + (lane & 3)*2;
                    float vx = acc[mt][nt][2*half + 0] + bias[col];
                    float vy = acc[mt][nt][2*half + 1] + bias[col + 1];
                    const int which = col >> 9;          // 0=q 1=k 2=v
                    const int head  = (col & 511) >> 5;
                    const int d     = col & 31;
                    const size_t o  = base + (size_t)head*(NT*HD) + d;
                    if (which == 0) {
                        *(__half2*)(g_q + o) =
                            __halves2half2(__float2half_rn(vx * QK_SCALE),
                                           __float2half_rn(vy * QK_SCALE));
                    } else if (which == 2) {
                        *(__half2*)(g_v + o) =
                            __halves2half2(__float2half_rn(vx), __float2half_rn(vy));
                    } else {
                        __half h0 = __float2half_rn(vx);
                        __half h1 = __float2half_rn(vy);
                        __half l0 = __float2half_rn(vx - __half2float(h0));
                        __half l1 = __float2half_rn(vy - __half2float(h1));
                        *(__half2*)(g_kh + o) = __halves2half2(h0, h1);
                        *(__half2*)(g_kl + o) = __halves2half2(l0, l1);
                    }
                }
            }
    }
}

// ---------------- HMMA attention: register P, fp16 combined bias+mask ----------
// 224 threads = 7 warps; warp wid owns output rows wid*16..wid*16+15.
#define AP      112
#define AT_Q  0
#define AT_KH (AP*64)
#define AT_KL (2*AP*64)
#define AT_V  (3*AP*64)
#define AT_BYTES (4*AP*64)      // 28672

__global__ __launch_bounds__(224)
void attn_mma_kernel() {
    extern __shared__ char sm[];
    const int tid  = threadIdx.x;
    const int lane = tid & 31;
    const int wid  = tid >> 5;
    const int bh = blockIdx.x;
    const int b  = bh >> 4;
    const int h  = bh & 15;
    const int w  = b & (NWIN - 1);
    const uint32_t sb = smem_u32(sm);

    // ---- fill q, k(hi/lo), v tiles; zero pad rows 98..111
    {
        const __half* gsrc[4] = { g_q, g_kh, g_kl, g_v };
        const size_t gbase = (size_t)bh * (NT*HD);
        for (int c = tid; c < 4*AP*4; c += 224) {
            int mat = c / (AP*4);
            int rem = c % (AP*4);
            int row = rem >> 2, q = rem & 3;
            uint4 val = make_uint4(0, 0, 0, 0);
            if (row < NT)
                val = *(const uint4*)(gsrc[mat] + gbase + (size_t)row*HD + q*8);
            *(uint4*)(sm + mat*AP*64 + sw_off(row, q)) = val;
        }
    }
    __syncthreads();

    const int lr  = lane & 15;
    const int lq2 = lane >> 4;

    // ---- S = Q K^T (q single, k hi/lo)
    uint32_t qf[2][4];
    #pragma unroll
    for (int ks = 0; ks < 2; ks++) {
        uint32_t off = sw_off(wid*16 + lr, 2*ks + lq2);
        ldsm_x4(qf[ks][0], qf[ks][1], qf[ks][2], qf[ks][3], sb + AT_Q + off);
    }
    float c[7][2][4];
    #pragma unroll
    for (int nt = 0; nt < 7; nt++)
        #pragma unroll
        for (int n8 = 0; n8 < 2; n8++)
            #pragma unroll
            for (int e = 0; e < 4; e++) c[nt][n8][e] = 0.f;

    #pragma unroll
    for (int nt = 0; nt < 7; nt++) {
        #pragma unroll
        for (int ks = 0; ks < 2; ks++) {
            uint32_t t0, t1, t2, t3, u0, u1, u2, u3;
            uint32_t off = sw_off(nt*16 + lr, 2*ks + lq2);
            ldsm_x4(t0, t1, t2, t3, sb + AT_KH + off);
            ldsm_x4(u0, u1, u2, u3, sb + AT_KL + off);
            uint32_t kh0[2] = {t0, t2}, kh1[2] = {t1, t3};
            uint32_t kl0[2] = {u0, u2}, kl1[2] = {u1, u3};
            mma_f16(c[nt][0], qf[ks], kh0);
            mma_f16(c[nt][0], qf[ks], kl0);
            mma_f16(c[nt][1], qf[ks], kh1);
            mma_f16(c[nt][1], qf[ks], kl1);
        }
    }

    // ---- fused combined bias+mask (fp16 plane), register softmax
    const int i0 = wid*16 + (lane >> 2);
    const int i1 = i0 + 8;
    const __half* bm = g_bm + (size_t)(w*NH + h) * (NT*NT);
    #pragma unroll
    for (int nt = 0; nt < 7; nt++)
        #pragma unroll
        for (int n8 = 0; n8 < 2; n8++) {
            int col = nt*16 + n8*8 + (lane & 3)*2;
            if (col < NT && i0 < NT) {
                float2 f = __half22float2(*(const __half2*)(bm + (size_t)i0*NT + col));
                c[nt][n8][0] += f.x;
                c[nt][n8][1] += f.y;
            } else { c[nt][n8][0] = -1e30f; c[nt][n8][1] = -1e30f; }
            if (col < NT && i1 < NT) {
                float2 f = __half22float2(*(const __half2*)(bm + (size_t)i1*NT + col));
                c[nt][n8][2] += f.x;
                c[nt][n8][3] += f.y;
            } else { c[nt][n8][2] = -1e30f; c[nt][n8][3] = -1e30f; }
        }

    float mx0 = -1e30f, mx1 = -1e30f;
    #pragma unroll
    for (int nt = 0; nt < 7; nt++)
        #pragma unroll
        for (int n8 = 0; n8 < 2; n8++) {
            mx0 = fmaxf(mx0, fmaxf(c[nt][n8][0], c[nt][n8][1]));
            mx1 = fmaxf(mx1, fmaxf(c[nt][n8][2], c[nt][n8][3]));
        }
    #pragma unroll
    for (int off = 1; off <= 2; off <<= 1) {
        mx0 = fmaxf(mx0, __shfl_xor_sync(0xffffffffu, mx0, off));
        mx1 = fmaxf(mx1, __shfl_xor_sync(0xffffffffu, mx1, off));
    }
    float s0 = 0.f, s1 = 0.f;
    #pragma unroll
    for (int nt = 0; nt < 7; nt++)
        #pragma unroll
        for (int n8 = 0; n8 < 2; n8++) {
            float e0 = __expf(c[nt][n8][0] - mx0);
            float e1 = __expf(c[nt][n8][1] - mx0);
            float e2 = __expf(c[nt][n8][2] - mx1);
            float e3 = __expf(c[nt][n8][3] - mx1);
            c[nt][n8][0] = e0; c[nt][n8][1] = e1;
            c[nt][n8][2] = e2; c[nt][n8][3] = e3;
            s0 += e0 + e1; s1 += e2 + e3;
        }
    #pragma unroll
    for (int off = 1; off <= 2; off <<= 1) {
        s0 += __shfl_xor_sync(0xffffffffu, s0, off);
        s1 += __shfl_xor_sync(0xffffffffu, s1, off);
    }
    const float r0 = 1.f / s0, r1 = 1.f / s1;

    // ---- convert P c-frags -> PV a-frags in registers
    uint32_t pa[7][4];
    #pragma unroll
    for (int nt = 0; nt < 7; nt++) {
        pa[nt][0] = packh2(c[nt][0][0] * r0, c[nt][0][1] * r0);
        pa[nt][1] = packh2(c[nt][0][2] * r1, c[nt][0][3] * r1);
        pa[nt][2] = packh2(c[nt][1][0] * r0, c[nt][1][1] * r0);
        pa[nt][3] = packh2(c[nt][1][2] * r1, c[nt][1][3] * r1);
    }

    // ---- out = P V
    float oc[4][4];
    #pragma unroll
    for (int j = 0; j < 4; j++)
        #pragma unroll
        for (int e = 0; e < 4; e++) oc[j][e] = 0.f;

    #pragma unroll
    for (int kt = 0; kt < 7; kt++) {
        #pragma unroll
        for (int vt = 0; vt < 2; vt++) {
            uint32_t t0, t1, t2, t3;
            ldsm_x4_t(t0, t1, t2, t3, sb + AT_V + sw_off(kt*16 + lr, vt*2 + lq2));
            uint32_t b0[2] = {t0, t1}, b1[2] = {t2, t3};
            mma_f16(oc[vt*2 + 0], pa[kt], b0);
            mma_f16(oc[vt*2 + 1], pa[kt], b1);
        }
    }

    // ---- store (fp16, proj-input layout)
    #pragma unroll
    for (int j = 0; j < 4; j++) {
        const int d = j*8 + (lane & 3)*2;
        if (i0 < NT)
            *(__half2*)(g_o + (size_t)(b*NT + i0)*DIMC + h*HD + d) =
                __halves2half2(__float2half_rn(oc[j][0]), __float2half_rn(oc[j][1]));
        if (i1 < NT)
            *(__half2*)(g_o + (size_t)(b*NT + i1)*DIMC + h*HD + d) =
                __halves2half2(__float2half_rn(oc[j][2]), __float2half_rn(oc[j][3]));
    }
}

// ---------------- launch --------------------------------------------------------
extern "C" void kernel_launch(void* const* d_in, const int* in_sizes, int n_in,
                              void* d_out, int out_size) {
    const float* x          = (const float*)d_in[0];
    const float* mask       = (const float*)d_in[1];
    const float* qkv_w      = (const float*)d_in[2];
    const float* qkv_b      = (const float*)d_in[3];
    const float* proj_w     = (const float*)d_in[4];
    const float* proj_b     = (const float*)d_in[5];
    const float* bias_table = (const float*)d_in[6];
    const int*   rel_index  = (const int*)  d_in[7];
    float* out = (float*)d_out;

    cudaFuncSetAttribute(attn_mma_kernel,
                         cudaFuncAttributeMaxDynamicSharedMemorySize, AT_BYTES);
    cudaFuncSetAttribute(gemm_mma<0>,
                         cudaFuncAttributeMaxDynamicSharedMemorySize, SMEM_GEMM);
    cudaFuncSetAttribute(gemm_mma<1>,
                         cudaFuncAttributeMaxDynamicSharedMemorySize, SMEM_GEMM);

    pre_kernel<<<PRE_BLOCKS, 256>>>(x, qkv_w, proj_w, mask, bias_table, rel_index);
    gemm_mma<1><<<dim3(3*DIMC/128, MROWS/128), 256, SMEM_GEMM>>>(qkv_b, nullptr);
    attn_mma_kernel<<<NB*NH, 224, AT_BYTES>>>();
    gemm_mma<0><<<dim3(DIMC/128, MROWS/128), 256, SMEM_GEMM>>>(proj_b, out);
}

// round 17
// speedup vs baseline: 1.2299x; 1.0197x over previous
#include <cuda_runtime.h>
#include <cuda_fp16.h>
#include <math.h>
#include <stdint.h>

#define NB    512
#define NT    98
#define DIMC  512
#define NH    16
#define HD    32
#define NWIN  64
#define MROWS (NB*NT)                 // 50176
#define QK_SCALE 0.17677669529663687f
#define LOG2E    1.44269504088896341f

// ---------------- scratch (device globals; no runtime alloc) ---------------
__device__ __align__(16) __half g_x [(size_t)MROWS*DIMC];    // x fp16
__device__ __align__(16) __half g_w [(size_t)3*DIMC*DIMC];   // qkv_w fp16
__device__ __align__(16) __half g_p [(size_t)DIMC*DIMC];     // proj_w fp16
__device__ __align__(16) __half g_o [(size_t)MROWS*DIMC];    // attn out fp16

// q single, k hi/lo, v single fp16; layout [(b*NH+h)*NT + n][HD]
__device__ __align__(16) __half g_q [(size_t)NB*NH*NT*HD];
__device__ __align__(16) __half g_kh[(size_t)NB*NH*NT*HD];
__device__ __align__(16) __half g_kl[(size_t)NB*NH*NT*HD];
__device__ __align__(16) __half g_v [(size_t)NB*NH*NT*HD];

// combined (bias+mask)*log2e, fp16: [w][h][i][j]
__device__ __align__(16) __half g_bm[(size_t)NWIN*NH*NT*NT];

// ---------------- helpers ----------------------------------------------------
__device__ __forceinline__ uint32_t smem_u32(const void* p) {
    uint32_t a;
    asm("{ .reg .u64 t; cvta.to.shared.u64 t, %1; cvt.u32.u64 %0, t; }"
        : "=r"(a) : "l"(p));
    return a;
}
__device__ __forceinline__ void ldsm_x4(uint32_t& r0, uint32_t& r1,
                                        uint32_t& r2, uint32_t& r3, uint32_t addr) {
    asm volatile("ldmatrix.sync.aligned.m8n8.x4.shared.b16 {%0,%1,%2,%3}, [%4];"
                 : "=r"(r0), "=r"(r1), "=r"(r2), "=r"(r3) : "r"(addr));
}
__device__ __forceinline__ void ldsm_x4_t(uint32_t& r0, uint32_t& r1,
                                          uint32_t& r2, uint32_t& r3, uint32_t addr) {
    asm volatile("ldmatrix.sync.aligned.m8n8.x4.trans.shared.b16 {%0,%1,%2,%3}, [%4];"
                 : "=r"(r0), "=r"(r1), "=r"(r2), "=r"(r3) : "r"(addr));
}
__device__ __forceinline__ void mma_f16(float* c, const uint32_t* a, const uint32_t* b) {
    asm volatile(
        "mma.sync.aligned.m16n8k16.row.col.f32.f16.f16.f32 "
        "{%0,%1,%2,%3}, {%4,%5,%6,%7}, {%8,%9}, {%0,%1,%2,%3};"
        : "+f"(c[0]), "+f"(c[1]), "+f"(c[2]), "+f"(c[3])
        : "r"(a[0]), "r"(a[1]), "r"(a[2]), "r"(a[3]), "r"(b[0]), "r"(b[1]));
}
__device__ __forceinline__ void cpa16(uint32_t saddr, const void* g) {
    asm volatile("cp.async.cg.shared.global [%0], [%1], 16;"
                 :: "r"(saddr), "l"(g) : "memory");
}
__device__ __forceinline__ void cpa16z(uint32_t saddr, const void* g, uint32_t nbytes) {
    asm volatile("cp.async.cg.shared.global [%0], [%1], 16, %2;"
                 :: "r"(saddr), "l"(g), "r"(nbytes) : "memory");
}
__device__ __forceinline__ uint32_t packh2(float a, float b) {
    __half2 h = __halves2half2(__float2half_rn(a), __float2half_rn(b));
    return *(uint32_t*)&h;
}
__device__ __forceinline__ float ex2f(float x) {
    float r;
    asm("ex2.approx.f32 %0, %1;" : "=f"(r) : "f"(x));
    return r;
}
// 64B-row tile swizzle (attention tiles)
__device__ __forceinline__ uint32_t sw_off(int row, int q) {
    return (uint32_t)(row * 64 + ((q ^ ((row >> 1) & 3)) << 4));
}
// 128B-row tile swizzle (GEMM tiles)
__device__ __forceinline__ uint32_t sw128o(int row, int q) {
    return (uint32_t)(row * 128 + ((q ^ (row & 7)) << 4));
}

// ---------------- fused preprocessing: converts + combined bias/mask ----------
#define N8X  (MROWS*DIMC/8)
#define N8W  (3*DIMC*DIMC/8)
#define N8P  (DIMC*DIMC/8)
#define BX   (N8X/256)
#define BW   (N8W/256)
#define BP   (N8P/256)
#define BBM  (NWIN*NH)
#define PRE_BLOCKS (BX + BW + BP + BBM)

__global__ void pre_kernel(const float* __restrict__ x,
                           const float* __restrict__ qkv_w,
                           const float* __restrict__ proj_w,
                           const float* __restrict__ mask,
                           const float* __restrict__ bt,
                           const int*   __restrict__ ri) {
    int blk = blockIdx.x;
    if (blk < BX + BW + BP) {
        const float* src;
        __half2* dst;
        int i;
        if (blk < BX)            { src = x;      dst = (__half2*)g_x; i = blk*256 + threadIdx.x; }
        else if (blk < BX + BW)  { src = qkv_w;  dst = (__half2*)g_w; i = (blk-BX)*256 + threadIdx.x; }
        else                     { src = proj_w; dst = (__half2*)g_p; i = (blk-BX-BW)*256 + threadIdx.x; }
        float4 a = ((const float4*)src)[2*i];
        float4 b = ((const float4*)src)[2*i + 1];
        dst[4*i + 0] = __halves2half2(__float2half_rn(a.x), __float2half_rn(a.y));
        dst[4*i + 1] = __halves2half2(__float2half_rn(a.z), __float2half_rn(a.w));
        dst[4*i + 2] = __halves2half2(__float2half_rn(b.x), __float2half_rn(b.y));
        dst[4*i + 3] = __halves2half2(__float2half_rn(b.z), __float2half_rn(b.w));
    } else {
        // combined (bias+mask)*log2e plane for one (w,h)
        const int blk2 = blk - (BX + BW + BP);
        const int w = blk2 >> 4;
        const int h = blk2 & 15;
        const float* mk = mask + (size_t)w * (NT*NT);
        __half* dst = g_bm + (size_t)blk2 * (NT*NT);
        for (int ij = threadIdx.x; ij < NT*NT; ij += 256)
            dst[ij] = __float2half_rn((bt[ri[ij]*NH + h] + mk[ij]) * LOG2E);
    }
}

// ---------------- HMMA fp16 GEMM (R13 shape) -----------------------------------
#define KCH      64
#define NCHUNK   (DIMC / KCH)        // 8
#define TILE_B2  16384               // 128 rows x 128B
#define STAGE_B  (2 * TILE_B2)       // A + B = 32 KB
#define NSTAGE   3
#define SMEM_GEMM (NSTAGE * STAGE_B) // 96 KB

template<int MODE>
__global__ __launch_bounds__(256, 2)
void gemm_mma(const float* __restrict__ bias, float* __restrict__ C) {
    extern __shared__ char smem[];
    const int tid  = threadIdx.x;
    const int lane = tid & 31;
    const int wid  = tid >> 5;
    const int wm   = wid >> 2;
    const int wn   = wid & 3;
    const int m0 = blockIdx.y * 128;
    const int n0 = blockIdx.x * 128;

    const __half* A = (MODE == 1) ? g_x : g_o;
    const __half* B = (MODE == 1) ? g_w : g_p;

    const uint32_t sb = smem_u32(smem);

    float acc[4][4][4];
    #pragma unroll
    for (int i = 0; i < 4; i++)
        #pragma unroll
        for (int j = 0; j < 4; j++)
            #pragma unroll
            for (int k = 0; k < 4; k++) acc[i][j][k] = 0.f;

    #define FILL_STAGE(SBASE, K0)                                               \
        {                                                                       \
            _Pragma("unroll")                                                   \
            for (int t = 0; t < 4; t++) {                                       \
                int u = tid + 256*t;                                            \
                int row = u >> 3, q = u & 7;                                    \
                cpa16((SBASE) + sw128o(row, q),                                 \
                      A + (size_t)(m0 + row)*DIMC + (K0) + q*8);                \
                cpa16((SBASE) + TILE_B2 + sw128o(row, q),                       \
                      B + (size_t)(n0 + row)*DIMC + (K0) + q*8);                \
            }                                                                   \
        }

    FILL_STAGE(sb + 0*STAGE_B, 0);
    asm volatile("cp.async.commit_group;" ::: "memory");
    FILL_STAGE(sb + 1*STAGE_B, KCH);
    asm volatile("cp.async.commit_group;" ::: "memory");

    const int lr  = lane & 15;
    const int lq2 = lane >> 4;
    int stage = 0;

    for (int c = 0; c < NCHUNK; c++) {
        asm volatile("cp.async.wait_group 1;" ::: "memory");
        __syncthreads();

        if (c + 2 < NCHUNK) {
            int ps = stage + 2; if (ps >= NSTAGE) ps -= NSTAGE;
            FILL_STAGE(sb + ps*STAGE_B, (c + 2)*KCH);
        }
        asm volatile("cp.async.commit_group;" ::: "memory");

        const uint32_t tba = sb + (uint32_t)stage * STAGE_B;
        #pragma unroll
        for (int ks = 0; ks < 4; ks++) {
            const int qq = ks*2 + lq2;
            uint32_t af[4][4], bf[4][2];
            #pragma unroll
            for (int mt = 0; mt < 4; mt++) {
                uint32_t off = sw128o(wm*64 + mt*16 + lr, qq);
                ldsm_x4(af[mt][0], af[mt][1], af[mt][2], af[mt][3], tba + off);
            }
            #pragma unroll
            for (int g2 = 0; g2 < 2; g2++) {
                uint32_t off = sw128o(wn*32 + g2*16 + lr, qq);
                uint32_t t0, t1, t2, t3;
                ldsm_x4(t0, t1, t2, t3, tba + TILE_B2 + off);
                bf[2*g2][0] = t0; bf[2*g2][1] = t2;
                bf[2*g2+1][0] = t1; bf[2*g2+1][1] = t3;
            }
            #pragma unroll
            for (int mt = 0; mt < 4; mt++)
                #pragma unroll
                for (int nt = 0; nt < 4; nt++)
                    mma_f16(acc[mt][nt], af[mt], bf[nt]);
        }
        stage++; if (stage >= NSTAGE) stage -= NSTAGE;
    }
    #undef FILL_STAGE

    // ---- epilogue
    if (MODE == 0) {
        #pragma unroll
        for (int mt = 0; mt < 4; mt++)
            #pragma unroll
            for (int nt = 0; nt < 4; nt++) {
                const int col = n0 + wn*32 + nt*8 + (lane & 3)*2;
                const float b0 = bias[col], b1 = bias[col + 1];
                #pragma unroll
                for (int half = 0; half < 2; half++) {
                    const int row = m0 + wm*64 + mt*16 + (lane >> 2) + half*8;
                    *(float2*)(C + (size_t)row*DIMC + col) =
                        make_float2(acc[mt][nt][2*half] + b0,
                                    acc[mt][nt][2*half + 1] + b1);
                }
            }
    } else {
        #pragma unroll
        for (int mt = 0; mt < 4; mt++)
            #pragma unroll
            for (int half = 0; half < 2; half++) {
                const int row = m0 + wm*64 + mt*16 + (lane >> 2) + half*8;
                const int b = row / NT;
                const int n = row - b*NT;
                const size_t base = ((size_t)b*NH*NT + n)*HD;
                #pragma unroll
                for (int nt = 0; nt < 4; nt++) {
                    const int col = n0 + wn*32 + nt*8 + (lane & 3)*2;
                    float vx = acc[mt][nt][2*half + 0] + bias[col];
                    float vy = acc[mt][nt][2*half + 1] + bias[col + 1];
                    const int which = col >> 9;          // 0=q 1=k 2=v
                    const int head  = (col & 511) >> 5;
                    const int d     = col & 31;
                    const size_t o  = base + (size_t)head*(NT*HD) + d;
                    if (which == 0) {
                        *(__half2*)(g_q + o) =
                            __halves2half2(__float2half_rn(vx * QK_SCALE),
                                           __float2half_rn(vy * QK_SCALE));
                    } else if (which == 2) {
                        *(__half2*)(g_v + o) =
                            __halves2half2(__float2half_rn(vx), __float2half_rn(vy));
                    } else {
                        __half h0 = __float2half_rn(vx);
                        __half h1 = __float2half_rn(vy);
                        __half l0 = __float2half_rn(vx - __half2float(h0));
                        __half l1 = __float2half_rn(vy - __half2float(h1));
                        *(__half2*)(g_kh + o) = __halves2half2(h0, h1);
                        *(__half2*)(g_kl + o) = __halves2half2(l0, l1);
                    }
                }
            }
    }
}

// ---------------- HMMA attention: exp2 softmax, MMA row-sum --------------------
// 224 threads = 7 warps; warp wid owns output rows wid*16..wid*16+15.
#define AP      112
#define AT_Q  0
#define AT_KH (AP*64)
#define AT_KL (2*AP*64)
#define AT_V  (3*AP*64)
#define AT_BYTES (4*AP*64)      // 28672

__global__ __launch_bounds__(224)
void attn_mma_kernel() {
    extern __shared__ char sm[];
    const int tid  = threadIdx.x;
    const int lane = tid & 31;
    const int wid  = tid >> 5;
    const int bh = blockIdx.x;
    const int b  = bh >> 4;
    const int h  = bh & 15;
    const int w  = b & (NWIN - 1);
    const uint32_t sb = smem_u32(sm);

    // ---- fill q, k(hi/lo), v tiles via cp.async (zfill pads rows 98..111)
    {
        const __half* gsrc[4] = { g_q, g_kh, g_kl, g_v };
        const size_t gbase = (size_t)bh * (NT*HD);
        for (int c = tid; c < 4*AP*4; c += 224) {
            int mat = c / (AP*4);
            int rem = c % (AP*4);
            int row = rem >> 2, q = rem & 3;
            cpa16z(sb + mat*AP*64 + sw_off(row, q),
                   gsrc[mat] + gbase + (size_t)row*HD + q*8,
                   (row < NT) ? 16u : 0u);
        }
        asm volatile("cp.async.commit_group;" ::: "memory");
        asm volatile("cp.async.wait_group 0;" ::: "memory");
    }
    __syncthreads();

    const int lr  = lane & 15;
    const int lq2 = lane >> 4;

    // ---- S = Q K^T (q single, k hi/lo)
    uint32_t qf[2][4];
    #pragma unroll
    for (int ks = 0; ks < 2; ks++) {
        uint32_t off = sw_off(wid*16 + lr, 2*ks + lq2);
        ldsm_x4(qf[ks][0], qf[ks][1], qf[ks][2], qf[ks][3], sb + AT_Q + off);
    }
    float c[7][2][4];
    #pragma unroll
    for (int nt = 0; nt < 7; nt++)
        #pragma unroll
        for (int n8 = 0; n8 < 2; n8++)
            #pragma unroll
            for (int e = 0; e < 4; e++) c[nt][n8][e] = 0.f;

    #pragma unroll
    for (int nt = 0; nt < 7; nt++) {
        #pragma unroll
        for (int ks = 0; ks < 2; ks++) {
            uint32_t t0, t1, t2, t3, u0, u1, u2, u3;
            uint32_t off = sw_off(nt*16 + lr, 2*ks + lq2);
            ldsm_x4(t0, t1, t2, t3, sb + AT_KH + off);
            ldsm_x4(u0, u1, u2, u3, sb + AT_KL + off);
            uint32_t kh0[2] = {t0, t2}, kh1[2] = {t1, t3};
            uint32_t kl0[2] = {u0, u2}, kl1[2] = {u1, u3};
            mma_f16(c[nt][0], qf[ks], kh0);
            mma_f16(c[nt][0], qf[ks], kl0);
            mma_f16(c[nt][1], qf[ks], kh1);
            mma_f16(c[nt][1], qf[ks], kl1);
        }
    }

    // ---- logits in exp2 domain: c*log2e + bm_l (bm prescaled by log2e)
    const int i0 = wid*16 + (lane >> 2);
    const int i1 = i0 + 8;
    const __half* bm = g_bm + (size_t)(w*NH + h) * (NT*NT);
    #pragma unroll
    for (int nt = 0; nt < 7; nt++)
        #pragma unroll
        for (int n8 = 0; n8 < 2; n8++) {
            int col = nt*16 + n8*8 + (lane & 3)*2;
            if (col < NT && i0 < NT) {
                float2 f = __half22float2(*(const __half2*)(bm + (size_t)i0*NT + col));
                c[nt][n8][0] = fmaf(c[nt][n8][0], LOG2E, f.x);
                c[nt][n8][1] = fmaf(c[nt][n8][1], LOG2E, f.y);
            } else { c[nt][n8][0] = -1e30f; c[nt][n8][1] = -1e30f; }
            if (col < NT && i1 < NT) {
                float2 f = __half22float2(*(const __half2*)(bm + (size_t)i1*NT + col));
                c[nt][n8][2] = fmaf(c[nt][n8][2], LOG2E, f.x);
                c[nt][n8][3] = fmaf(c[nt][n8][3], LOG2E, f.y);
            } else { c[nt][n8][2] = -1e30f; c[nt][n8][3] = -1e30f; }
        }

    float mx0 = -1e30f, mx1 = -1e30f;
    #pragma unroll
    for (int nt = 0; nt < 7; nt++)
        #pragma unroll
        for (int n8 = 0; n8 < 2; n8++) {
            mx0 = fmaxf(mx0, fmaxf(c[nt][n8][0], c[nt][n8][1]));
            mx1 = fmaxf(mx1, fmaxf(c[nt][n8][2], c[nt][n8][3]));
        }
    #pragma unroll
    for (int off = 1; off <= 2; off <<= 1) {
        mx0 = fmaxf(mx0, __shfl_xor_sync(0xffffffffu, mx0, off));
        mx1 = fmaxf(mx1, __shfl_xor_sync(0xffffffffu, mx1, off));
    }

    // ---- P = exp2(c - mx), packed directly to fp16 a-frags (unnormalized)
    uint32_t pa[7][4];
    #pragma unroll
    for (int nt = 0; nt < 7; nt++) {
        pa[nt][0] = packh2(ex2f(c[nt][0][0] - mx0), ex2f(c[nt][0][1] - mx0));
        pa[nt][1] = packh2(ex2f(c[nt][0][2] - mx1), ex2f(c[nt][0][3] - mx1));
        pa[nt][2] = packh2(ex2f(c[nt][1][0] - mx0), ex2f(c[nt][1][1] - mx0));
        pa[nt][3] = packh2(ex2f(c[nt][1][2] - mx1), ex2f(c[nt][1][3] - mx1));
    }

    // ---- out = P V; row-sum via ones B-frag
    float oc[4][4];
    #pragma unroll
    for (int j = 0; j < 4; j++)
        #pragma unroll
        for (int e = 0; e < 4; e++) oc[j][e] = 0.f;
    float osum[4] = {0.f, 0.f, 0.f, 0.f};
    const uint32_t onesb[2] = {0x3C003C00u, 0x3C003C00u};

    #pragma unroll
    for (int kt = 0; kt < 7; kt++) {
        #pragma unroll
        for (int vt = 0; vt < 2; vt++) {
            uint32_t t0, t1, t2, t3;
            ldsm_x4_t(t0, t1, t2, t3, sb + AT_V + sw_off(kt*16 + lr, vt*2 + lq2));
            uint32_t b0[2] = {t0, t1}, b1[2] = {t2, t3};
            mma_f16(oc[vt*2 + 0], pa[kt], b0);
            mma_f16(oc[vt*2 + 1], pa[kt], b1);
        }
        mma_f16(osum, pa[kt], onesb);
    }
    const float r0 = 1.f / osum[0];
    const float r1 = 1.f / osum[2];

    // ---- store (fp16, proj-input layout), normalized here
    #pragma unroll
    for (int j = 0; j < 4; j++) {
        const int d = j*8 + (lane & 3)*2;
        if (i0 < NT)
            *(__half2*)(g_o + (size_t)(b*NT + i0)*DIMC + h*HD + d) =
                __halves2half2(__float2half_rn(oc[j][0] * r0),
                               __float2half_rn(oc[j][1] * r0));
        if (i1 < NT)
            *(__half2*)(g_o + (size_t)(b*NT + i1)*DIMC + h*HD + d) =
                __halves2half2(__float2half_rn(oc[j][2] * r1),
                               __float2half_rn(oc[j][3] * r1));
    }
}

// ---------------- launch --------------------------------------------------------
extern "C" void kernel_launch(void* const* d_in, const int* in_sizes, int n_in,
                              void* d_out, int out_size) {
    const float* x          = (const float*)d_in[0];
    const float* mask       = (const float*)d_in[1];
    const float* qkv_w      = (const float*)d_in[2];
    const float* qkv_b      = (const float*)d_in[3];
    const float* proj_w     = (const float*)d_in[4];
    const float* proj_b     = (const float*)d_in[5];
    const float* bias_table = (const float*)d_in[6];
    const int*   rel_index  = (const int*)  d_in[7];
    float* out = (float*)d_out;

    cudaFuncSetAttribute(attn_mma_kernel,
                         cudaFuncAttributeMaxDynamicSharedMemorySize, AT_BYTES);
    cudaFuncSetAttribute(gemm_mma<0>,
                         cudaFuncAttributeMaxDynamicSharedMemorySize, SMEM_GEMM);
    cudaFuncSetAttribute(gemm_mma<1>,
                         cudaFuncAttributeMaxDynamicSharedMemorySize, SMEM_GEMM);

    pre_kernel<<<PRE_BLOCKS, 256>>>(x, qkv_w, proj_w, mask, bias_table, rel_index);
    gemm_mma<1><<<dim3(3*DIMC/128, MROWS/128), 256, SMEM_GEMM>>>(qkv_b, nullptr);
    attn_mma_kernel<<<NB*NH, 224, AT_BYTES>>>();
    gemm_mma<0><<<dim3(DIMC/128, MROWS/128), 256, SMEM_GEMM>>>(proj_b, out);
}